// round 17
// baseline (speedup 1.0000x reference)
#include <cuda_runtime.h>
#include <cuda_fp16.h>
#include <math.h>

#define TOKENS_M 16384   // B*N
#define CTX_M    4096    // B*M
#define EMB      1024
#define CTXD     768
#define NHEAD    16
#define HDIM     64
#define SEQ_N    4096
#define SEQ_M    1024
#define KVLD     2048    // combined K|V row stride
#define SCALE_L2E 0.1803368801111244f   // HEAD_DIM^-0.5 * log2(e)

// fp16 scratch (static device globals)
__device__ __half g_ht[TOKENS_M * EMB];
__device__ __half g_hc[CTX_M * CTXD];
__device__ __half g_hwq[EMB * EMB];        // [k=1024][n=1024]
__device__ __half g_hwkv[CTXD * KVLD];     // [k=768][n=2048]  (Wk | Wv)
__device__ __half g_hwo[EMB * EMB];        // [k=1024][n=1024]
__device__ __half g_hQ[TOKENS_M * EMB];
__device__ __half g_hKV[CTX_M * KVLD];     // [row][K 0..1023 | V 1024..2047]
__device__ __half g_hA[TOKENS_M * EMB];

__device__ __forceinline__ float ex2f(float x) {
    float y;
    asm("ex2.approx.ftz.f32 %0, %1;" : "=f"(y) : "f"(x));
    return y;
}
__device__ __forceinline__ unsigned packh2(float lo, float hi) {
    __half2 h = __floats2half2_rn(lo, hi);
    return *reinterpret_cast<unsigned*>(&h);
}
__device__ __forceinline__ unsigned s2u(const void* p) {
    return (unsigned)__cvta_generic_to_shared(p);
}
__device__ __forceinline__ void cp16(unsigned dst, const void* src) {
    asm volatile("cp.async.cg.shared.global [%0], [%1], 16;" :: "r"(dst), "l"(src));
}
__device__ __forceinline__ void cp_commit() {
    asm volatile("cp.async.commit_group;");
}
template<int N> __device__ __forceinline__ void cp_wait() {
    asm volatile("cp.async.wait_group %0;" :: "n"(N));
}
__device__ __forceinline__ void ldsm4(unsigned* r, unsigned a) {
    asm volatile("ldmatrix.sync.aligned.m8n8.x4.shared.b16 {%0,%1,%2,%3}, [%4];"
        : "=r"(r[0]), "=r"(r[1]), "=r"(r[2]), "=r"(r[3]) : "r"(a));
}
__device__ __forceinline__ void ldsm4t(unsigned* r, unsigned a) {
    asm volatile("ldmatrix.sync.aligned.m8n8.x4.trans.shared.b16 {%0,%1,%2,%3}, [%4];"
        : "=r"(r[0]), "=r"(r[1]), "=r"(r[2]), "=r"(r[3]) : "r"(a));
}
__device__ __forceinline__ void mma_f16(
    float& c0, float& c1, float& c2, float& c3,
    unsigned a0, unsigned a1, unsigned a2, unsigned a3,
    unsigned b0, unsigned b1)
{
    asm volatile(
        "mma.sync.aligned.m16n8k16.row.col.f32.f16.f16.f32 "
        "{%0,%1,%2,%3}, {%4,%5,%6,%7}, {%8,%9}, {%0,%1,%2,%3};"
        : "+f"(c0), "+f"(c1), "+f"(c2), "+f"(c3)
        : "r"(a0), "r"(a1), "r"(a2), "r"(a3), "r"(b0), "r"(b1));
}

// ---------------------------------------------------------------------------
// Fused fp32 -> fp16 convert, 6 segments, with optional row remap so
// Wk/Wv interleave into the combined [k][2048] layout.
// ---------------------------------------------------------------------------
struct Cvt6 {
    const float4* s[6];
    uint2*        d[6];
    int           n4[6];
    int           rowN4[6];
    int           dstStride[6];
    int           colOff[6];
    float         scale[6];
};

__global__ void f2h6(Cvt6 c)
{
    int i = blockIdx.x * blockDim.x + threadIdx.x;
#pragma unroll
    for (int seg = 0; seg < 6; seg++) {
        if (i < c.n4[seg]) {
            float4 v = c.s[seg][i];
            const float sc = c.scale[seg];
            uint2 u;
            u.x = packh2(v.x * sc, v.y * sc);
            u.y = packh2(v.z * sc, v.w * sc);
            const int row = i / c.rowN4[seg];
            const int rem = i - row * c.rowN4[seg];
            c.d[seg][(size_t)row * c.dstStride[seg] + c.colOff[seg] + rem] = u;
            return;
        }
        i -= c.n4[seg];
    }
}

// ---------------------------------------------------------------------------
// fp16 GEMM body: C[M,N] = A[M,K] @ B[K,N] (+bias), fp32 accum.  (R16 proven)
// BM=BN=128, BK=64, 256 thr, warps 2m x 4n, warp tile 64x32.
// 3-stage cp.async pipeline, ONE __syncthreads per iteration, 2 blocks/SM.
// ---------------------------------------------------------------------------
#define ASH 72     // A row stride (halves)
#define BSH 136    // B row stride (halves)
#define GSTAGE (128 * ASH + 64 * BSH)        // halves per stage (17920)
#define GEMM_SMEM (3 * GSTAGE * 2)           // bytes (107520)

template<bool HOUT>
__device__ __forceinline__ void gemm_body(
    const __half* __restrict__ A, const __half* __restrict__ B,
    void* __restrict__ Cv, int M, int N, int K, const float* __restrict__ bias,
    int bx, int by, __half* gsm)
{
    const int tid  = threadIdx.x;
    const int lane = tid & 31;
    const int wid  = tid >> 5;
    const int wm   = (wid >> 2) * 64;
    const int wn   = (wid & 3) * 32;

    float acc[4][4][4];
#pragma unroll
    for (int mt = 0; mt < 4; mt++)
#pragma unroll
        for (int nt = 0; nt < 4; nt++)
#pragma unroll
            for (int c = 0; c < 4; c++) acc[mt][nt][c] = 0.f;

    auto issue = [&](int st, int k0) {
        __half* as = gsm + st * GSTAGE;
        __half* bs = as + 128 * ASH;
#pragma unroll
        for (int i = 0; i < 4; i++) {         // A: 128x64 halves
            const int idx = tid + 256 * i;
            const int r = idx >> 3, c = idx & 7;
            cp16(s2u(as + r * ASH + c * 8),
                 A + (size_t)(by + r) * K + k0 + c * 8);
        }
#pragma unroll
        for (int i = 0; i < 4; i++) {         // B: 64x128 halves
            const int idx = tid + 256 * i;
            const int r = idx >> 4, c = idx & 15;
            cp16(s2u(bs + r * BSH + c * 8),
                 B + (size_t)(k0 + r) * N + bx + c * 8);
        }
        cp_commit();
    };

    const int nk = K >> 6;
    issue(0, 0);
    if (nk > 1) issue(1, 64);

    for (int it = 0; it < nk; it++) {
        if (it + 1 < nk) cp_wait<1>(); else cp_wait<0>();
        __syncthreads();
        if (it + 2 < nk) issue((it + 2) % 3, (it + 2) << 6);

        const __half* as = gsm + (it % 3) * GSTAGE;
        const __half* bs = as + 128 * ASH;

#pragma unroll
        for (int kg = 0; kg < 2; kg++) {
            unsigned bfr[4][4];
#pragma unroll
            for (int nt = 0; nt < 4; nt++)
                ldsm4t(bfr[nt], s2u(bs + (kg * 32 + lane) * BSH + wn + nt * 8));
#pragma unroll
            for (int ks2 = 0; ks2 < 2; ks2++) {
                const int ks = kg * 2 + ks2;
                unsigned afr[4][4];
#pragma unroll
                for (int mt = 0; mt < 4; mt++)
                    ldsm4(afr[mt], s2u(as + (wm + mt * 16 + (lane & 15)) * ASH
                                          + ks * 16 + ((lane >> 4) << 3)));
#pragma unroll
                for (int mt = 0; mt < 4; mt++)
#pragma unroll
                    for (int nt = 0; nt < 4; nt++)
                        mma_f16(acc[mt][nt][0], acc[mt][nt][1],
                                acc[mt][nt][2], acc[mt][nt][3],
                                afr[mt][0], afr[mt][1], afr[mt][2], afr[mt][3],
                                bfr[nt][2 * ks2], bfr[nt][2 * ks2 + 1]);
            }
        }
    }

#pragma unroll
    for (int mt = 0; mt < 4; mt++) {
        const int r0 = by + wm + mt * 16 + (lane >> 2);
#pragma unroll
        for (int nt = 0; nt < 4; nt++) {
            const int col = bx + wn + nt * 8 + 2 * (lane & 3);
            if (HOUT) {
                __half* C = (__half*)Cv;
                *(__half2*)(C + (size_t)r0 * N + col) =
                    __floats2half2_rn(acc[mt][nt][0], acc[mt][nt][1]);
                *(__half2*)(C + (size_t)(r0 + 8) * N + col) =
                    __floats2half2_rn(acc[mt][nt][2], acc[mt][nt][3]);
            } else {
                float* C = (float*)Cv;
                const float bv0 = bias ? bias[col] : 0.f;
                const float bv1 = bias ? bias[col + 1] : 0.f;
                float2 v0 = { acc[mt][nt][0] + bv0, acc[mt][nt][1] + bv1 };
                float2 v1 = { acc[mt][nt][2] + bv0, acc[mt][nt][3] + bv1 };
                *(float2*)(C + (size_t)r0 * N + col) = v0;
                *(float2*)(C + (size_t)(r0 + 8) * N + col) = v1;
            }
        }
    }
}

// Dual-job projection kernel: Q-proj and KV-proj in one launch.
struct GemmJob {
    const __half* A;
    const __half* B;
    __half*       C;
    int M, N, K, nbx;
};

__global__ __launch_bounds__(256, 2) void gemm_dual(GemmJob j0, GemmJob j1,
                                                    int blocks0)
{
    extern __shared__ __half gsm[];
    GemmJob j;
    int b;
    if ((int)blockIdx.x < blocks0) { j = j0; b = blockIdx.x; }
    else                           { j = j1; b = blockIdx.x - blocks0; }
    const int bx = (b % j.nbx) * 128;
    const int by = (b / j.nbx) * 128;
    gemm_body<true>(j.A, j.B, j.C, j.M, j.N, j.K, nullptr, bx, by, gsm);
}

// Single GEMM kernel (fp32 out + bias) for the output projection.
__global__ __launch_bounds__(256, 2) void gemm_bias(
    const __half* __restrict__ A, const __half* __restrict__ B,
    float* __restrict__ C, int M, int N, int K, const float* __restrict__ bias)
{
    extern __shared__ __half gsm[];
    gemm_body<false>(A, B, C, M, N, K, bias,
                     blockIdx.x * 128, blockIdx.y * 128, gsm);
}

// ---------------------------------------------------------------------------
// fp16 flash attention, STATIC softmax, warp m-tile 32 (q-tile 256/block),
// INTERLEAVED phases: S(keys 0-31) -> ex2(0-31) -> S(32-63) -> PV(0-31)
// -> ex2(32-63) -> PV(32-63), so MUFU softmax overlaps tensor mma work.
// grid=(SEQ_N/256, NHEAD, B), 256 thr, 1 block/SM.
// ---------------------------------------------------------------------------
#define QSH 72
#define KVBUF (2 * 64 * QSH)
#define ATTN_SMEM (3 * KVBUF * 2)

__global__ __launch_bounds__(256) void attn_tc(
    const __half* __restrict__ Qg, const __half* __restrict__ KVg,
    __half* __restrict__ Og)
{
    extern __shared__ __half sm[];

    const int tid    = threadIdx.x;
    const int lane   = tid & 31;
    const int wid    = tid >> 5;
    const int qbase  = blockIdx.z * SEQ_N + blockIdx.x * 256;
    const int kvbase = blockIdx.z * SEQ_M;
    const int hcol   = blockIdx.y * HDIM;

    // ---- Stage Q (256x64) into KV buffers 0+1 region, hoist frags ----
#pragma unroll
    for (int i = 0; i < 8; i++) {
        const int idx = tid + 256 * i;
        const int r = idx >> 3, c = idx & 7;
        cp16(s2u(sm + r * QSH + c * 8),
             Qg + (size_t)(qbase + r) * EMB + hcol + c * 8);
    }
    cp_commit();
    cp_wait<0>();
    __syncthreads();

    unsigned aq[2][4][4];   // [mt][k16 step][frag]
#pragma unroll
    for (int mt = 0; mt < 2; mt++)
#pragma unroll
        for (int ks = 0; ks < 4; ks++)
            ldsm4(aq[mt][ks], s2u(sm + (wid * 32 + mt * 16 + (lane & 15)) * QSH
                                     + ks * 16 + ((lane >> 4) << 3)));
    __syncthreads();   // everyone done reading Q before KV overwrites

    auto issueKV = [&](int st, int kt) {
        __half* ks_ = sm + st * KVBUF;
        __half* vs_ = ks_ + 64 * QSH;
#pragma unroll
        for (int i = 0; i < 2; i++) {
            const int idx = tid + 256 * i;
            const int r = idx >> 3, c = idx & 7;
            cp16(s2u(ks_ + r * QSH + c * 8),
                 KVg + (size_t)(kvbase + kt + r) * KVLD + hcol + c * 8);
        }
#pragma unroll
        for (int i = 0; i < 2; i++) {
            const int idx = tid + 256 * i;
            const int r = idx >> 3, c = idx & 7;
            cp16(s2u(vs_ + r * QSH + c * 8),
                 KVg + (size_t)(kvbase + kt + r) * KVLD + 1024 + hcol + c * 8);
        }
        cp_commit();
    };

    issueKV(0, 0);
    issueKV(1, 64);

    float lrun[2][2] = { {0.f, 0.f}, {0.f, 0.f} };
    float oacc[2][8][4];
#pragma unroll
    for (int mt = 0; mt < 2; mt++)
#pragma unroll
        for (int nt = 0; nt < 8; nt++)
#pragma unroll
            for (int c = 0; c < 4; c++) oacc[mt][nt][c] = 0.f;

    const int NT = SEQ_M / 64;
    for (int it = 0; it < NT; it++) {
        if (it + 1 < NT) cp_wait<1>(); else cp_wait<0>();
        __syncthreads();
        if (it + 2 < NT) issueKV((it + 2) % 3, (it + 2) * 64);

        const __half* ks_ = sm + (it % 3) * KVBUF;
        const __half* vs_ = ks_ + 64 * QSH;

        float sacc[2][8][4];
#pragma unroll
        for (int mt = 0; mt < 2; mt++)
#pragma unroll
            for (int nt = 0; nt < 8; nt++)
#pragma unroll
                for (int c = 0; c < 4; c++) sacc[mt][nt][c] = 0.f;

        unsigned pexp[2][4][4];   // packed fp16 P fragments per k16 group

        // S phase for one key-half (keys ntc*32 .. ntc*32+31)
        auto s_half = [&](int ntc) {
#pragma unroll
            for (int g = 0; g < 2; g++) {
                unsigned kfr[4][4];
#pragma unroll
                for (int j = 0; j < 4; j++)
                    ldsm4(kfr[j], s2u(ks_ + ((ntc * 4 + j) * 8 + (lane & 7)) * QSH
                                          + g * 32 + ((lane >> 3) & 3) * 8));
#pragma unroll
                for (int h = 0; h < 2; h++) {
                    const int ks = 2 * g + h;
#pragma unroll
                    for (int j = 0; j < 4; j++)
#pragma unroll
                        for (int mt = 0; mt < 2; mt++)
                            mma_f16(sacc[mt][ntc * 4 + j][0], sacc[mt][ntc * 4 + j][1],
                                    sacc[mt][ntc * 4 + j][2], sacc[mt][ntc * 4 + j][3],
                                    aq[mt][ks][0], aq[mt][ks][1],
                                    aq[mt][ks][2], aq[mt][ks][3],
                                    kfr[j][2 * h], kfr[j][2 * h + 1]);
                }
            }
        };

        // ex2 + row-sum + pack for one key-half (ksi = 2*half, 2*half+1)
        auto exp_half = [&](int half) {
#pragma unroll
            for (int mt = 0; mt < 2; mt++)
#pragma unroll
                for (int ksi = 2 * half; ksi < 2 * half + 2; ksi++) {
                    const int n0 = 2 * ksi, n1 = 2 * ksi + 1;
                    sacc[mt][n0][0] = ex2f(sacc[mt][n0][0]);
                    sacc[mt][n0][1] = ex2f(sacc[mt][n0][1]);
                    sacc[mt][n0][2] = ex2f(sacc[mt][n0][2]);
                    sacc[mt][n0][3] = ex2f(sacc[mt][n0][3]);
                    sacc[mt][n1][0] = ex2f(sacc[mt][n1][0]);
                    sacc[mt][n1][1] = ex2f(sacc[mt][n1][1]);
                    sacc[mt][n1][2] = ex2f(sacc[mt][n1][2]);
                    sacc[mt][n1][3] = ex2f(sacc[mt][n1][3]);
                    lrun[mt][0] += sacc[mt][n0][0] + sacc[mt][n0][1]
                                 + sacc[mt][n1][0] + sacc[mt][n1][1];
                    lrun[mt][1] += sacc[mt][n0][2] + sacc[mt][n0][3]
                                 + sacc[mt][n1][2] + sacc[mt][n1][3];
                    pexp[mt][ksi][0] = packh2(sacc[mt][n0][0], sacc[mt][n0][1]);
                    pexp[mt][ksi][1] = packh2(sacc[mt][n0][2], sacc[mt][n0][3]);
                    pexp[mt][ksi][2] = packh2(sacc[mt][n1][0], sacc[mt][n1][1]);
                    pexp[mt][ksi][3] = packh2(sacc[mt][n1][2], sacc[mt][n1][3]);
                }
        };

        // PV phase for one key-half (keys g*32 .. g*32+31)
        auto pv_half = [&](int g) {
#pragma unroll
            for (int ntc = 0; ntc < 2; ntc++) {
                unsigned vfr[4][4];
#pragma unroll
                for (int j = 0; j < 4; j++)
                    ldsm4t(vfr[j], s2u(vs_ + (g * 32 + lane) * QSH
                                           + (ntc * 4 + j) * 8));
#pragma unroll
                for (int h = 0; h < 2; h++) {
                    const int ksi = 2 * g + h;
#pragma unroll
                    for (int j = 0; j < 4; j++)
#pragma unroll
                        for (int mt = 0; mt < 2; mt++)
                            mma_f16(oacc[mt][ntc * 4 + j][0], oacc[mt][ntc * 4 + j][1],
                                    oacc[mt][ntc * 4 + j][2], oacc[mt][ntc * 4 + j][3],
                                    pexp[mt][ksi][0], pexp[mt][ksi][1],
                                    pexp[mt][ksi][2], pexp[mt][ksi][3],
                                    vfr[j][2 * h], vfr[j][2 * h + 1]);
                }
            }
        };

        // Interleaved schedule: MUFU softmax overlaps tensor mma phases.
        s_half(0);
        exp_half(0);
        s_half(1);
        pv_half(0);
        exp_half(1);
        pv_half(1);
    }

    // Epilogue: quad-reduce row sums once, normalize, write fp16.
#pragma unroll
    for (int mt = 0; mt < 2; mt++) {
        float l0 = lrun[mt][0], l1 = lrun[mt][1];
        l0 += __shfl_xor_sync(0xffffffffu, l0, 1);
        l0 += __shfl_xor_sync(0xffffffffu, l0, 2);
        l1 += __shfl_xor_sync(0xffffffffu, l1, 1);
        l1 += __shfl_xor_sync(0xffffffffu, l1, 2);
        const float inv0 = 1.f / l0;
        const float inv1 = 1.f / l1;
        const int r0 = qbase + wid * 32 + mt * 16 + (lane >> 2);
#pragma unroll
        for (int nt = 0; nt < 8; nt++) {
            const int col = hcol + nt * 8 + 2 * (lane & 3);
            *(__half2*)(Og + (size_t)r0 * EMB + col) =
                __floats2half2_rn(oacc[mt][nt][0] * inv0, oacc[mt][nt][1] * inv0);
            *(__half2*)(Og + (size_t)(r0 + 8) * EMB + col) =
                __floats2half2_rn(oacc[mt][nt][2] * inv1, oacc[mt][nt][3] * inv1);
        }
    }
}

// ---------------------------------------------------------------------------
extern "C" void kernel_launch(void* const* d_in, const int* in_sizes, int n_in,
                              void* d_out, int out_size)
{
    const float* tokens  = (const float*)d_in[0];
    const float* context = (const float*)d_in[1];
    const float* Wq      = (const float*)d_in[2];
    const float* Wk      = (const float*)d_in[3];
    const float* Wv      = (const float*)d_in[4];
    const float* Wo      = (const float*)d_in[5];
    const float* bo      = (const float*)d_in[6];
    float* out = (float*)d_out;

    __half *ht, *hc, *hwq, *hwkv, *hwo, *hQ, *hKV, *hA;
    cudaGetSymbolAddress((void**)&ht,   g_ht);
    cudaGetSymbolAddress((void**)&hc,   g_hc);
    cudaGetSymbolAddress((void**)&hwq,  g_hwq);
    cudaGetSymbolAddress((void**)&hwkv, g_hwkv);
    cudaGetSymbolAddress((void**)&hwo,  g_hwo);
    cudaGetSymbolAddress((void**)&hQ,   g_hQ);
    cudaGetSymbolAddress((void**)&hKV,  g_hKV);
    cudaGetSymbolAddress((void**)&hA,   g_hA);

    cudaFuncSetAttribute(gemm_dual,
                         cudaFuncAttributeMaxDynamicSharedMemorySize, GEMM_SMEM);
    cudaFuncSetAttribute(gemm_bias,
                         cudaFuncAttributeMaxDynamicSharedMemorySize, GEMM_SMEM);
    cudaFuncSetAttribute(attn_tc,
                         cudaFuncAttributeMaxDynamicSharedMemorySize, ATTN_SMEM);

    // Fused fp16 conversion (Wk/Wv remapped into combined [k][2048] layout)
    Cvt6 cv;
    cv.s[0] = (const float4*)tokens;  cv.d[0] = (uint2*)ht;
    cv.n4[0] = TOKENS_M * EMB / 4;    cv.rowN4[0] = cv.n4[0];
    cv.dstStride[0] = 0;              cv.colOff[0] = 0;  cv.scale[0] = 1.f;
    cv.s[1] = (const float4*)context; cv.d[1] = (uint2*)hc;
    cv.n4[1] = CTX_M * CTXD / 4;      cv.rowN4[1] = cv.n4[1];
    cv.dstStride[1] = 0;              cv.colOff[1] = 0;  cv.scale[1] = 1.f;
    cv.s[2] = (const float4*)Wq;      cv.d[2] = (uint2*)hwq;
    cv.n4[2] = EMB * EMB / 4;         cv.rowN4[2] = cv.n4[2];
    cv.dstStride[2] = 0;              cv.colOff[2] = 0;  cv.scale[2] = SCALE_L2E;
    cv.s[3] = (const float4*)Wk;      cv.d[3] = (uint2*)hwkv;
    cv.n4[3] = CTXD * EMB / 4;        cv.rowN4[3] = EMB / 4;
    cv.dstStride[3] = KVLD / 4;       cv.colOff[3] = 0;  cv.scale[3] = 1.f;
    cv.s[4] = (const float4*)Wv;      cv.d[4] = (uint2*)hwkv;
    cv.n4[4] = CTXD * EMB / 4;        cv.rowN4[4] = EMB / 4;
    cv.dstStride[4] = KVLD / 4;       cv.colOff[4] = EMB / 4;  cv.scale[4] = 1.f;
    cv.s[5] = (const float4*)Wo;      cv.d[5] = (uint2*)hwo;
    cv.n4[5] = EMB * EMB / 4;         cv.rowN4[5] = cv.n4[5];
    cv.dstStride[5] = 0;              cv.colOff[5] = 0;  cv.scale[5] = 1.f;
    int total4 = 0;
    for (int i = 0; i < 6; i++) total4 += cv.n4[i];
    f2h6<<<(total4 + 255) / 256, 256>>>(cv);

    // Q projection + combined K|V projection, one dual-job launch
    GemmJob jq  = { ht, hwq,  hQ,  TOKENS_M, EMB,  EMB,  EMB / 128 };
    GemmJob jkv = { hc, hwkv, hKV, CTX_M,    KVLD, CTXD, KVLD / 128 };
    const int blocksQ  = (TOKENS_M / 128) * (EMB / 128);   // 1024
    const int blocksKV = (CTX_M / 128) * (KVLD / 128);     // 512
    gemm_dual<<<blocksQ + blocksKV, 256, GEMM_SMEM>>>(jq, jkv, blocksQ);

    // Fused attention (static softmax, interleaved phases)
    attn_tc<<<dim3(SEQ_N / 256, NHEAD, 4), 256, ATTN_SMEM>>>(hQ, hKV, hA);

    // Output projection + bias (fp32 out)
    gemm_bias<<<dim3(EMB / 128, TOKENS_M / 128), 256, GEMM_SMEM>>>(
        hA, hwo, out, TOKENS_M, EMB, EMB, bo);
}